// round 4
// baseline (speedup 1.0000x reference)
#include <cuda_runtime.h>

#define NUMLAB 670000
#define Bn 128
#define Cn 65536
#define Mn 16
#define Hn 512
#define Kn 200
#define KMn 3200   // Kn*Mn
#define CAP 3072   // survivor buffer capacity per row
#define SBn 8      // scan blocks per row

// ---- scratch (no allocations allowed) ----
__device__ int      g_cnt[Bn];
__device__ unsigned g_surv_u[Bn * CAP];
__device__ int      g_surv_i[Bn * CAP];
__device__ int      g_cands[Bn * KMn];
__device__ float    g_cscores[Bn * KMn];

// monotone float->uint key: descending float == descending key
__device__ __forceinline__ unsigned fkey(float x) {
    unsigned u = __float_as_uint(x);
    return (u & 0x80000000u) ? ~u : (u | 0x80000000u);
}

// ============================================================
// Kernel 0: zero per-row survivor counters.
// ============================================================
__global__ void zero_kernel() {
    if (threadIdx.x < Bn) g_cnt[threadIdx.x] = 0;
}

// ============================================================
// Kernel 1: full-chip streaming collect. grid (SBn, Bn).
// Each block scans Cn/SBn elements of its row, pushing all
// elements >= fixed threshold (raw logit 2.5; ~400/row for
// N(0,1) rows) into the row's global survivor buffer.
// ============================================================
__global__ void __launch_bounds__(1024) collect_kernel(const float* __restrict__ logits) {
    const int row = blockIdx.y;
    const int seg = blockIdx.x;
    const int n4  = Cn / 4 / SBn;                 // float4s per block
    const float4* rp4 = (const float4*)(logits + (size_t)row * Cn) + seg * n4;
    const int base = seg * n4 * 4;
    const unsigned T0 = fkey(2.5f);

    for (int i = threadIdx.x; i < n4; i += 1024) {
        float4 v = rp4[i];
        float vals[4] = {v.x, v.y, v.z, v.w};
        #pragma unroll
        for (int t = 0; t < 4; t++) {
            unsigned u = fkey(vals[t]);
            if (u >= T0) {
                int p = atomicAdd(&g_cnt[row], 1);
                if (p < CAP) {
                    g_surv_u[row * CAP + p] = u;
                    g_surv_i[row * CAP + p] = base + i * 4 + t;
                }
            }
        }
    }
}

// ============================================================
// Kernel 2: per-row exact rank-select over survivors (value
// desc, index-asc ties) FUSED with cluster expansion + stable
// pad-compaction. One block (1024 thr) per row.
// Fallback (block-uniform trigger, m<Kn or m>CAP): exact 4x8bit
// radix select re-scanning the row, then re-collect — correct
// for any input distribution.
// ============================================================
__global__ void __launch_bounds__(1024) select_expand_kernel(const float* __restrict__ logits,
                                                             const int* __restrict__ clusters,
                                                             float* __restrict__ out) {
    const int row = blockIdx.x;
    const int tid = threadIdx.x;
    const float*  rp  = logits + (size_t)row * Cn;
    const float4* rp4 = (const float4*)rp;

    __shared__ unsigned s_bu[CAP];
    __shared__ int      s_bi[CAP];
    __shared__ int      s_tidx[Kn];
    __shared__ float    s_tsc[Kn];
    __shared__ int      s_scan[1024];
    __shared__ unsigned s_red[256];
    __shared__ unsigned s_prefix;
    __shared__ int      s_kneed;
    __shared__ int      s_cnt;

    int m = g_cnt[row];

    if (m >= Kn && m <= CAP) {
        for (int i = tid; i < m; i += 1024) {
            s_bu[i] = g_surv_u[row * CAP + i];
            s_bi[i] = g_surv_i[row * CAP + i];
        }
        __syncthreads();
    } else {
        // ---- fallback: exact radix select of the Kn-th largest key ----
        if (tid == 0) { s_prefix = 0u; s_kneed = Kn; s_cnt = 0; }
        __syncthreads();
        for (int shift = 24; shift >= 0; shift -= 8) {
            for (int b = tid; b < 256; b += 1024) s_red[b] = 0u;
            __syncthreads();
            const unsigned pref = s_prefix;
            const unsigned mhi  = (shift == 24) ? 0u : (0xFFFFFFFFu << (shift + 8));
            for (int i = tid; i < Cn / 4; i += 1024) {
                float4 v = rp4[i];
                float vals[4] = {v.x, v.y, v.z, v.w};
                #pragma unroll
                for (int t = 0; t < 4; t++) {
                    unsigned u = fkey(vals[t]);
                    if ((u & mhi) == pref) atomicAdd(&s_red[(u >> shift) & 255], 1u);
                }
            }
            __syncthreads();
            if (tid == 0) {
                int kneed = s_kneed;
                int cum = 0;
                int b = 255;
                for (; b > 0; b--) {
                    int c = (int)s_red[b];
                    if (cum + c >= kneed) break;
                    cum += c;
                }
                s_kneed  = kneed - cum;
                s_prefix = pref | ((unsigned)b << shift);
            }
            __syncthreads();
        }
        const unsigned T = s_prefix;
        for (int i = tid; i < Cn / 4; i += 1024) {
            float4 v = rp4[i];
            float vals[4] = {v.x, v.y, v.z, v.w};
            #pragma unroll
            for (int t = 0; t < 4; t++) {
                unsigned u = fkey(vals[t]);
                if (u >= T) {
                    int p = atomicAdd(&s_cnt, 1);
                    if (p < CAP) { s_bu[p] = u; s_bi[p] = i * 4 + t; }
                }
            }
        }
        __syncthreads();
        m = min(s_cnt, CAP);
    }

    // ---- exact rank-select: rank = #{j : u_j>u_i or (u_j==u_i && idx_j<idx_i)} ----
    for (int i = tid; i < m; i += 1024) {
        const unsigned ui = s_bu[i];
        const int xi = s_bi[i];
        int r = 0;
        for (int j = 0; j < m; j++) {
            const unsigned uj = s_bu[j];
            if (uj > ui || (uj == ui && s_bi[j] < xi)) r++;
        }
        if (r < Kn) {
            float v = rp[xi];
            s_tidx[r] = xi;
            s_tsc[r]  = 1.f / (1.f + __expf(-v));
        }
    }
    __syncthreads();

    // ---- expand clusters + stable pad-compaction ----
    int cand[4];
    int valid[4];
    float sc = 0.f;
    const int base = tid * 4;
    int nv = 0;
    if (base < KMn) {
        const int j = base >> 4;                 // 4 | 16 => same topk slot for all 4
        const int idx = min(max(s_tidx[j], 0), Cn - 1);
        sc = s_tsc[j];
        const int mb = base & 15;
        #pragma unroll
        for (int t = 0; t < 4; t++) {
            int c = clusters[(size_t)idx * Mn + mb + t];
            cand[t]  = c;
            valid[t] = (c != NUMLAB);
            nv += valid[t];
        }
    }
    s_scan[tid] = nv;
    __syncthreads();
    for (int off = 1; off < 1024; off <<= 1) {
        int v = (tid >= off) ? s_scan[tid - off] : 0;
        __syncthreads();
        s_scan[tid] += v;
        __syncthreads();
    }
    const int total = s_scan[1023];
    const int excl  = s_scan[tid] - nv;

    if (base < KMn) {
        int vb = excl;  // valids strictly before current element
        #pragma unroll
        for (int t = 0; t < 4; t++) {
            int pos;
            if (valid[t]) { pos = vb; vb++; }
            else          { pos = total + (base + t) - vb; }
            g_cands[row * KMn + pos]   = cand[t];
            g_cscores[row * KMn + pos] = valid[t] ? sc : 0.f;
            out[(size_t)row * KMn + pos] = (float)cand[t];
        }
    }
}

// ============================================================
// Kernel 3: gather embeddings + dot with h_c, sigmoid, outputs.
// Warp per candidate (4 per warp), h_c row in smem.
// ============================================================
__global__ void __launch_bounds__(256) score_kernel(const float* __restrict__ h_c,
                                                    const float* __restrict__ table,
                                                    float* __restrict__ out) {
    const int row = blockIdx.y;
    __shared__ float sh[Hn];
    for (int i = threadIdx.x; i < Hn; i += 256) sh[i] = h_c[(size_t)row * Hn + i];
    __syncthreads();

    const int warp = threadIdx.x >> 5;
    const int lane = threadIdx.x & 31;
    const int c0 = blockIdx.x * 32 + warp * 4;
    const float4* hv = (const float4*)sh;

    for (int t = 0; t < 4; t++) {
        const int c = c0 + t;
        int label = g_cands[row * KMn + c];
        label = min(max(label, 0), NUMLAB);
        const float4* er = (const float4*)(table + (size_t)label * Hn);
        float acc = 0.f;
        #pragma unroll
        for (int i = 0; i < 4; i++) {
            float4 e = er[lane + i * 32];
            float4 h = hv[lane + i * 32];
            acc += e.x * h.x;
            acc += e.y * h.y;
            acc += e.z * h.z;
            acc += e.w * h.w;
        }
        #pragma unroll
        for (int off = 16; off; off >>= 1)
            acc += __shfl_xor_sync(0xffffffffu, acc, off);
        if (lane == 0) {
            float s = (acc == 0.f) ? 0.f : (1.f / (1.f + __expf(-acc)));
            out[(size_t)Bn * KMn     + (size_t)row * KMn + c] = s;
            out[(size_t)Bn * KMn * 2 + (size_t)row * KMn + c] = s * g_cscores[row * KMn + c];
        }
    }
}

extern "C" void kernel_launch(void* const* d_in, const int* in_sizes, int n_in,
                              void* d_out, int out_size) {
    // Bind inputs by element count (robust to metadata ordering):
    //   meta_logits  128*65536   = 8388608   f32
    //   h_c          128*512     = 65536     f32
    //   embed_table  670001*512  = 343040512 f32
    //   label_clusters 65536*16  = 1048576   i32 (jax x64 disabled -> int32)
    const float* meta = nullptr;
    const float* hc = nullptr;
    const float* table = nullptr;
    const int* clusters = nullptr;
    for (int i = 0; i < n_in; i++) {
        switch (in_sizes[i]) {
            case 8388608:   meta     = (const float*)d_in[i]; break;
            case 65536:     hc       = (const float*)d_in[i]; break;
            case 343040512: table    = (const float*)d_in[i]; break;
            case 1048576:   clusters = (const int*)d_in[i];   break;
            default: break; // topk scalar etc.
        }
    }
    float* out = (float*)d_out; // 3 * 128 * 3200 f32: [cands | cand_scores | product]

    zero_kernel<<<1, 128>>>();
    dim3 g1(SBn, Bn);
    collect_kernel<<<g1, 1024>>>(meta);
    select_expand_kernel<<<Bn, 1024>>>(meta, clusters, out);
    dim3 g3(KMn / 32, Bn);
    score_kernel<<<g3, 256>>>(hc, table, out);
}

// round 5
// speedup vs baseline: 1.1382x; 1.1382x over previous
#include <cuda_runtime.h>

#define NUMLAB 670000
#define Bn 128
#define Cn 65536
#define Mn 16
#define Hn 512
#define Kn 200
#define KMn 3200        // Kn*Mn
#define SBn 16          // scan segments per row
#define SEGCAP 256      // survivor capacity per segment (expected ~25)
#define ROWCAP (SBn * SEGCAP)  // 4096

// ---- scratch (no allocations allowed) ----
__device__ int      g_scnt[Bn * SBn];
__device__ unsigned g_su[Bn * SBn * SEGCAP];
__device__ int      g_si[Bn * SBn * SEGCAP];
__device__ int      g_cands[Bn * KMn];
__device__ float    g_cscores[Bn * KMn];

// monotone float->uint key: descending float == descending key
__device__ __forceinline__ unsigned fkey(float x) {
    unsigned u = __float_as_uint(x);
    return (u & 0x80000000u) ? ~u : (u | 0x80000000u);
}

// ============================================================
// Kernel 1: full-chip streaming collect. grid (SBn, Bn), 512 thr.
// Each block scans Cn/SBn = 4096 elements of its row; survivors
// (raw logit > 2.5, ~25 expected per segment) staged in smem via
// smem atomics, then dumped coalesced into a private per-segment
// global slot. Count written unconditionally (no zeroing pass,
// no global atomics anywhere).
// ============================================================
__global__ void __launch_bounds__(512) collect_kernel(const float* __restrict__ logits) {
    const int row = blockIdx.y;
    const int seg = blockIdx.x;
    const int n4  = Cn / 4 / SBn;                 // 1024 float4 per block
    const float4* rp4 = (const float4*)(logits + (size_t)row * Cn) + seg * n4;
    const int base = seg * n4 * 4;

    __shared__ unsigned s_u[SEGCAP];
    __shared__ int      s_i[SEGCAP];
    __shared__ int      s_cnt;
    if (threadIdx.x == 0) s_cnt = 0;
    __syncthreads();

    #pragma unroll
    for (int it = 0; it < 2; it++) {
        const int i = it * 512 + threadIdx.x;
        float4 v = rp4[i];
        float vals[4] = {v.x, v.y, v.z, v.w};
        #pragma unroll
        for (int t = 0; t < 4; t++) {
            if (vals[t] > 2.5f) {
                int p = atomicAdd(&s_cnt, 1);
                if (p < SEGCAP) { s_u[p] = fkey(vals[t]); s_i[p] = base + i * 4 + t; }
            }
        }
    }
    __syncthreads();
    const int c  = s_cnt;
    const int cc = min(c, SEGCAP);
    const size_t off = (size_t)(row * SBn + seg) * SEGCAP;
    for (int i = threadIdx.x; i < cc; i += 512) {
        g_su[off + i] = s_u[i];
        g_si[off + i] = s_i[i];
    }
    if (threadIdx.x == 0) g_scnt[row * SBn + seg] = c;
}

// ============================================================
// Kernel 2: per-row exact top-200 rank-select over survivors
// (value desc, index-asc ties) FUSED with cluster expansion +
// stable pad-compaction. One block (1024 thr) per row.
// Fallback (block-uniform trigger: any segment overflow, or
// total < Kn): exact 4x8-bit radix select re-scanning the row.
// ============================================================
__global__ void __launch_bounds__(1024) select_expand_kernel(const float* __restrict__ logits,
                                                             const int* __restrict__ clusters,
                                                             float* __restrict__ out) {
    const int row = blockIdx.x;
    const int tid = threadIdx.x;
    const float*  rp  = logits + (size_t)row * Cn;
    const float4* rp4 = (const float4*)rp;

    __shared__ unsigned s_bu[ROWCAP];      // 16 KB
    __shared__ int      s_bi[ROWCAP];      // 16 KB
    __shared__ int      s_segoff[SBn + 1];
    __shared__ int      s_tidx[Kn];
    __shared__ float    s_tsc[Kn];
    __shared__ int      s_scan[1024];
    __shared__ unsigned s_red[256];
    __shared__ unsigned s_prefix;
    __shared__ int      s_kneed;
    __shared__ int      s_cnt;
    __shared__ int      s_bad;

    // gather segment counts, prefix, overflow check
    if (tid == 0) {
        int acc = 0, bad = 0;
        #pragma unroll
        for (int s = 0; s < SBn; s++) {
            s_segoff[s] = acc;
            int c = g_scnt[row * SBn + s];
            if (c > SEGCAP) bad = 1;
            acc += min(c, SEGCAP);
        }
        s_segoff[SBn] = acc;
        if (acc < Kn) bad = 1;
        s_bad = bad;
    }
    __syncthreads();

    int m;
    if (!s_bad) {
        m = s_segoff[SBn];
        // coalesced gather of all segments into contiguous smem
        for (int s = tid >> 6; s < SBn; s += 16) {        // 16 warps-pairs: 64 threads/segment
            const int lt = tid & 63;
            const int cnt = s_segoff[s + 1] - s_segoff[s];
            const size_t off = (size_t)(row * SBn + s) * SEGCAP;
            for (int i = lt; i < cnt; i += 64) {
                s_bu[s_segoff[s] + i] = g_su[off + i];
                s_bi[s_segoff[s] + i] = g_si[off + i];
            }
        }
        __syncthreads();
    } else {
        // ---- fallback: exact radix select of the Kn-th largest key ----
        if (tid == 0) { s_prefix = 0u; s_kneed = Kn; s_cnt = 0; }
        __syncthreads();
        for (int shift = 24; shift >= 0; shift -= 8) {
            for (int b = tid; b < 256; b += 1024) s_red[b] = 0u;
            __syncthreads();
            const unsigned pref = s_prefix;
            const unsigned mhi  = (shift == 24) ? 0u : (0xFFFFFFFFu << (shift + 8));
            for (int i = tid; i < Cn / 4; i += 1024) {
                float4 v = rp4[i];
                float vals[4] = {v.x, v.y, v.z, v.w};
                #pragma unroll
                for (int t = 0; t < 4; t++) {
                    unsigned u = fkey(vals[t]);
                    if ((u & mhi) == pref) atomicAdd(&s_red[(u >> shift) & 255], 1u);
                }
            }
            __syncthreads();
            if (tid == 0) {
                int kneed = s_kneed;
                int cum = 0;
                int b = 255;
                for (; b > 0; b--) {
                    int c = (int)s_red[b];
                    if (cum + c >= kneed) break;
                    cum += c;
                }
                s_kneed  = kneed - cum;
                s_prefix = pref | ((unsigned)b << shift);
            }
            __syncthreads();
        }
        const unsigned T = s_prefix;
        for (int i = tid; i < Cn / 4; i += 1024) {
            float4 v = rp4[i];
            float vals[4] = {v.x, v.y, v.z, v.w};
            #pragma unroll
            for (int t = 0; t < 4; t++) {
                unsigned u = fkey(vals[t]);
                if (u >= T) {
                    int p = atomicAdd(&s_cnt, 1);
                    if (p < ROWCAP) { s_bu[p] = u; s_bi[p] = i * 4 + t; }
                }
            }
        }
        __syncthreads();
        m = min(s_cnt, ROWCAP);
    }

    // ---- exact rank-select: rank = #{j : u_j>u_i or (u_j==u_i && idx_j<idx_i)} ----
    for (int i = tid; i < m; i += 1024) {
        const unsigned ui = s_bu[i];
        const int xi = s_bi[i];
        int r = 0;
        for (int j = 0; j < m; j++) {
            const unsigned uj = s_bu[j];
            if (uj > ui || (uj == ui && s_bi[j] < xi)) r++;
        }
        if (r < Kn) {
            float v = rp[xi];
            s_tidx[r] = xi;
            s_tsc[r]  = 1.f / (1.f + __expf(-v));
        }
    }
    __syncthreads();

    // ---- expand clusters + stable pad-compaction ----
    int cand[4];
    int valid[4];
    float sc = 0.f;
    const int base = tid * 4;
    int nv = 0;
    if (base < KMn) {
        const int j = base >> 4;                 // 4 | 16 => same topk slot for all 4
        const int idx = min(max(s_tidx[j], 0), Cn - 1);
        sc = s_tsc[j];
        const int mb = base & 15;
        #pragma unroll
        for (int t = 0; t < 4; t++) {
            int c = clusters[(size_t)idx * Mn + mb + t];
            cand[t]  = c;
            valid[t] = (c != NUMLAB);
            nv += valid[t];
        }
    }
    s_scan[tid] = nv;
    __syncthreads();
    for (int off = 1; off < 1024; off <<= 1) {
        int v = (tid >= off) ? s_scan[tid - off] : 0;
        __syncthreads();
        s_scan[tid] += v;
        __syncthreads();
    }
    const int total = s_scan[1023];
    const int excl  = s_scan[tid] - nv;

    if (base < KMn) {
        int vb = excl;  // valids strictly before current element
        #pragma unroll
        for (int t = 0; t < 4; t++) {
            int pos;
            if (valid[t]) { pos = vb; vb++; }
            else          { pos = total + (base + t) - vb; }
            g_cands[row * KMn + pos]   = cand[t];
            g_cscores[row * KMn + pos] = valid[t] ? sc : 0.f;
            out[(size_t)row * KMn + pos] = (float)cand[t];
        }
    }
}

// ============================================================
// Kernel 3: gather embeddings + dot with h_c, sigmoid, outputs.
// Warp per candidate (4 per warp), h_c row in smem.
// (Measured at the LTS/DRAM cap — do not touch.)
// ============================================================
__global__ void __launch_bounds__(256) score_kernel(const float* __restrict__ h_c,
                                                    const float* __restrict__ table,
                                                    float* __restrict__ out) {
    const int row = blockIdx.y;
    __shared__ float sh[Hn];
    for (int i = threadIdx.x; i < Hn; i += 256) sh[i] = h_c[(size_t)row * Hn + i];
    __syncthreads();

    const int warp = threadIdx.x >> 5;
    const int lane = threadIdx.x & 31;
    const int c0 = blockIdx.x * 32 + warp * 4;
    const float4* hv = (const float4*)sh;

    for (int t = 0; t < 4; t++) {
        const int c = c0 + t;
        int label = g_cands[row * KMn + c];
        label = min(max(label, 0), NUMLAB);
        const float4* er = (const float4*)(table + (size_t)label * Hn);
        float acc = 0.f;
        #pragma unroll
        for (int i = 0; i < 4; i++) {
            float4 e = er[lane + i * 32];
            float4 h = hv[lane + i * 32];
            acc += e.x * h.x;
            acc += e.y * h.y;
            acc += e.z * h.z;
            acc += e.w * h.w;
        }
        #pragma unroll
        for (int off = 16; off; off >>= 1)
            acc += __shfl_xor_sync(0xffffffffu, acc, off);
        if (lane == 0) {
            float s = (acc == 0.f) ? 0.f : (1.f / (1.f + __expf(-acc)));
            out[(size_t)Bn * KMn     + (size_t)row * KMn + c] = s;
            out[(size_t)Bn * KMn * 2 + (size_t)row * KMn + c] = s * g_cscores[row * KMn + c];
        }
    }
}

extern "C" void kernel_launch(void* const* d_in, const int* in_sizes, int n_in,
                              void* d_out, int out_size) {
    // Bind inputs by element count (robust to metadata ordering):
    //   meta_logits  128*65536   = 8388608   f32
    //   h_c          128*512     = 65536     f32
    //   embed_table  670001*512  = 343040512 f32
    //   label_clusters 65536*16  = 1048576   i32 (jax x64 disabled -> int32)
    const float* meta = nullptr;
    const float* hc = nullptr;
    const float* table = nullptr;
    const int* clusters = nullptr;
    for (int i = 0; i < n_in; i++) {
        switch (in_sizes[i]) {
            case 8388608:   meta     = (const float*)d_in[i]; break;
            case 65536:     hc       = (const float*)d_in[i]; break;
            case 343040512: table    = (const float*)d_in[i]; break;
            case 1048576:   clusters = (const int*)d_in[i];   break;
            default: break; // topk scalar etc.
        }
    }
    float* out = (float*)d_out; // 3 * 128 * 3200 f32: [cands | cand_scores | product]

    dim3 g1(SBn, Bn);
    collect_kernel<<<g1, 512>>>(meta);
    select_expand_kernel<<<Bn, 1024>>>(meta, clusters, out);
    dim3 g3(KMn / 32, Bn);
    score_kernel<<<g3, 256>>>(hc, table, out);
}

// round 6
// speedup vs baseline: 1.1499x; 1.0103x over previous
#include <cuda_runtime.h>

#define NUMLAB 670000
#define Bn 128
#define Cn 65536
#define Mn 16
#define Hn 512
#define Kn 200
#define KMn 3200        // Kn*Mn
#define SBn 16          // scan segments per row
#define SEGCAP 256      // survivor capacity per segment (expected ~25)
#define ROWCAP (SBn * SEGCAP)  // 4096

// ---- scratch (no allocations allowed) ----
__device__ int      g_scnt[Bn * SBn];
__device__ unsigned g_su[Bn * SBn * SEGCAP];
__device__ int      g_si[Bn * SBn * SEGCAP];
__device__ int      g_cands[Bn * KMn];
__device__ float    g_cscores[Bn * KMn];

// monotone float->uint key: descending float == descending key
__device__ __forceinline__ unsigned fkey(float x) {
    unsigned u = __float_as_uint(x);
    return (u & 0x80000000u) ? ~u : (u | 0x80000000u);
}

// ============================================================
// Kernel 1: full-chip streaming collect. grid (SBn, Bn), 256 thr.
// Each thread front-loads 4 independent float4 (MLP=4), filters
// 16 values against the raw-logit threshold (2.5), stages the
// rare survivors in smem, dumps them coalesced to a private
// per-segment global slot. No global atomics.
// ============================================================
__global__ void __launch_bounds__(256) collect_kernel(const float* __restrict__ logits) {
    const int row = blockIdx.y;
    const int seg = blockIdx.x;
    const int n4  = Cn / 4 / SBn;                 // 1024 float4 per block
    const float4* rp4 = (const float4*)(logits + (size_t)row * Cn) + seg * n4;
    const int base = seg * n4 * 4;
    const int tid = threadIdx.x;

    __shared__ unsigned s_u[SEGCAP];
    __shared__ int      s_i[SEGCAP];
    __shared__ int      s_cnt;
    if (tid == 0) s_cnt = 0;
    __syncthreads();

    // 4 independent loads in flight
    float4 a0 = rp4[tid];
    float4 a1 = rp4[tid + 256];
    float4 a2 = rp4[tid + 512];
    float4 a3 = rp4[tid + 768];

    float vals[16] = {a0.x,a0.y,a0.z,a0.w, a1.x,a1.y,a1.z,a1.w,
                      a2.x,a2.y,a2.z,a2.w, a3.x,a3.y,a3.z,a3.w};
    #pragma unroll
    for (int t = 0; t < 16; t++) {
        if (vals[t] > 2.5f) {
            int p = atomicAdd(&s_cnt, 1);
            if (p < SEGCAP) {
                s_u[p] = fkey(vals[t]);
                s_i[p] = base + (t >> 2) * 1024 + tid * 4 + (t & 3);
            }
        }
    }
    __syncthreads();
    const int c  = s_cnt;
    const int cc = min(c, SEGCAP);
    const size_t off = (size_t)(row * SBn + seg) * SEGCAP;
    if (tid < cc) {
        g_su[off + tid] = s_u[tid];
        g_si[off + tid] = s_i[tid];
    }
    if (tid == 0) g_scnt[row * SBn + seg] = c;
}

// ============================================================
// Kernel 2: per-row exact top-200 rank-select over survivors
// (value desc, index-asc ties) FUSED with cluster expansion +
// stable pad-compaction. One block (1024 thr) per row.
// Fallback (block-uniform trigger: any segment overflow, or
// total < Kn): exact 4x8-bit radix select re-scanning the row.
// ============================================================
__global__ void __launch_bounds__(1024) select_expand_kernel(const float* __restrict__ logits,
                                                             const int* __restrict__ clusters,
                                                             float* __restrict__ out) {
    const int row = blockIdx.x;
    const int tid = threadIdx.x;
    const int lane = tid & 31;
    const int wid  = tid >> 5;
    const float*  rp  = logits + (size_t)row * Cn;
    const float4* rp4 = (const float4*)rp;

    __shared__ unsigned s_bu[ROWCAP];      // 16 KB
    __shared__ int      s_bi[ROWCAP];      // 16 KB
    __shared__ int      s_segcnt[SBn];
    __shared__ int      s_segoff[SBn + 1];
    __shared__ int      s_tidx[Kn];
    __shared__ float    s_tsc[Kn];
    __shared__ int      s_wsum[32];
    __shared__ int      s_total;
    __shared__ unsigned s_red[256];
    __shared__ unsigned s_prefix;
    __shared__ int      s_kneed;
    __shared__ int      s_cnt;
    __shared__ int      s_bad;

    // parallel load of per-segment counts
    if (tid < SBn) s_segcnt[tid] = g_scnt[row * SBn + tid];
    __syncthreads();
    if (tid == 0) {
        int acc = 0, bad = 0;
        #pragma unroll
        for (int s = 0; s < SBn; s++) {
            s_segoff[s] = acc;
            int c = s_segcnt[s];
            if (c > SEGCAP) bad = 1;
            acc += min(c, SEGCAP);
        }
        s_segoff[SBn] = acc;
        if (acc < Kn) bad = 1;
        s_bad = bad;
    }
    __syncthreads();

    int m;
    if (!s_bad) {
        m = s_segoff[SBn];
        // coalesced gather: 64 threads per segment
        {
            const int s  = tid >> 6;            // 0..15
            const int lt = tid & 63;
            const int cnt = s_segoff[s + 1] - s_segoff[s];
            const size_t off = (size_t)(row * SBn + s) * SEGCAP;
            for (int i = lt; i < cnt; i += 64) {
                s_bu[s_segoff[s] + i] = g_su[off + i];
                s_bi[s_segoff[s] + i] = g_si[off + i];
            }
        }
        __syncthreads();
    } else {
        // ---- fallback: exact radix select of the Kn-th largest key ----
        if (tid == 0) { s_prefix = 0u; s_kneed = Kn; s_cnt = 0; }
        __syncthreads();
        for (int shift = 24; shift >= 0; shift -= 8) {
            for (int b = tid; b < 256; b += 1024) s_red[b] = 0u;
            __syncthreads();
            const unsigned pref = s_prefix;
            const unsigned mhi  = (shift == 24) ? 0u : (0xFFFFFFFFu << (shift + 8));
            for (int i = tid; i < Cn / 4; i += 1024) {
                float4 v = rp4[i];
                float vals[4] = {v.x, v.y, v.z, v.w};
                #pragma unroll
                for (int t = 0; t < 4; t++) {
                    unsigned u = fkey(vals[t]);
                    if ((u & mhi) == pref) atomicAdd(&s_red[(u >> shift) & 255], 1u);
                }
            }
            __syncthreads();
            if (tid == 0) {
                int kneed = s_kneed;
                int cum = 0;
                int b = 255;
                for (; b > 0; b--) {
                    int c = (int)s_red[b];
                    if (cum + c >= kneed) break;
                    cum += c;
                }
                s_kneed  = kneed - cum;
                s_prefix = pref | ((unsigned)b << shift);
            }
            __syncthreads();
        }
        const unsigned T = s_prefix;
        for (int i = tid; i < Cn / 4; i += 1024) {
            float4 v = rp4[i];
            float vals[4] = {v.x, v.y, v.z, v.w};
            #pragma unroll
            for (int t = 0; t < 4; t++) {
                unsigned u = fkey(vals[t]);
                if (u >= T) {
                    int p = atomicAdd(&s_cnt, 1);
                    if (p < ROWCAP) { s_bu[p] = u; s_bi[p] = i * 4 + t; }
                }
            }
        }
        __syncthreads();
        m = min(s_cnt, ROWCAP);
    }

    // ---- exact rank-select: rank = #{j : u_j>u_i or (u_j==u_i && idx_j<idx_i)} ----
    for (int i = tid; i < m; i += 1024) {
        const unsigned ui = s_bu[i];
        const int xi = s_bi[i];
        int r = 0;
        for (int j = 0; j < m; j++) {
            const unsigned uj = s_bu[j];
            if (uj > ui || (uj == ui && s_bi[j] < xi)) r++;
        }
        if (r < Kn) {
            float v = rp[xi];
            s_tidx[r] = xi;
            s_tsc[r]  = 1.f / (1.f + __expf(-v));
        }
    }
    __syncthreads();

    // ---- expand clusters + stable pad-compaction ----
    int cand[4];
    int valid[4];
    float sc = 0.f;
    const int base = tid * 4;
    int nv = 0;
    if (base < KMn) {
        const int j = base >> 4;                 // 4 | 16 => same topk slot for all 4
        const int idx = min(max(s_tidx[j], 0), Cn - 1);
        sc = s_tsc[j];
        const int mb = base & 15;
        #pragma unroll
        for (int t = 0; t < 4; t++) {
            int c = clusters[(size_t)idx * Mn + mb + t];
            cand[t]  = c;
            valid[t] = (c != NUMLAB);
            nv += valid[t];
        }
    }
    // warp-shuffle inclusive scan of nv, then 32-warp scan in warp 0
    int x = nv;
    #pragma unroll
    for (int off = 1; off < 32; off <<= 1) {
        int y = __shfl_up_sync(0xffffffffu, x, off);
        if (lane >= off) x += y;
    }
    if (lane == 31) s_wsum[wid] = x;
    __syncthreads();
    if (tid < 32) {
        int v = s_wsum[tid];
        int inc = v;
        #pragma unroll
        for (int off = 1; off < 32; off <<= 1) {
            int y = __shfl_up_sync(0xffffffffu, inc, off);
            if (tid >= off) inc += y;
        }
        s_wsum[tid] = inc - v;   // exclusive warp offset
        if (tid == 31) s_total = inc;
    }
    __syncthreads();
    const int total = s_total;
    const int excl  = s_wsum[wid] + x - nv;

    if (base < KMn) {
        int vb = excl;  // valids strictly before current element
        #pragma unroll
        for (int t = 0; t < 4; t++) {
            int pos;
            if (valid[t]) { pos = vb; vb++; }
            else          { pos = total + (base + t) - vb; }
            g_cands[row * KMn + pos]   = cand[t];
            g_cscores[row * KMn + pos] = valid[t] ? sc : 0.f;
            out[(size_t)row * KMn + pos] = (float)cand[t];
        }
    }
}

// ============================================================
// Kernel 3: gather embeddings + dot with h_c, sigmoid, outputs.
// Warp per candidate (4 per warp), h_c row in smem.
// (Measured at the LTS/DRAM cap — do not touch.)
// ============================================================
__global__ void __launch_bounds__(256) score_kernel(const float* __restrict__ h_c,
                                                    const float* __restrict__ table,
                                                    float* __restrict__ out) {
    const int row = blockIdx.y;
    __shared__ float sh[Hn];
    for (int i = threadIdx.x; i < Hn; i += 256) sh[i] = h_c[(size_t)row * Hn + i];
    __syncthreads();

    const int warp = threadIdx.x >> 5;
    const int lane = threadIdx.x & 31;
    const int c0 = blockIdx.x * 32 + warp * 4;
    const float4* hv = (const float4*)sh;

    for (int t = 0; t < 4; t++) {
        const int c = c0 + t;
        int label = g_cands[row * KMn + c];
        label = min(max(label, 0), NUMLAB);
        const float4* er = (const float4*)(table + (size_t)label * Hn);
        float acc = 0.f;
        #pragma unroll
        for (int i = 0; i < 4; i++) {
            float4 e = er[lane + i * 32];
            float4 h = hv[lane + i * 32];
            acc += e.x * h.x;
            acc += e.y * h.y;
            acc += e.z * h.z;
            acc += e.w * h.w;
        }
        #pragma unroll
        for (int off = 16; off; off >>= 1)
            acc += __shfl_xor_sync(0xffffffffu, acc, off);
        if (lane == 0) {
            float s = (acc == 0.f) ? 0.f : (1.f / (1.f + __expf(-acc)));
            out[(size_t)Bn * KMn     + (size_t)row * KMn + c] = s;
            out[(size_t)Bn * KMn * 2 + (size_t)row * KMn + c] = s * g_cscores[row * KMn + c];
        }
    }
}

extern "C" void kernel_launch(void* const* d_in, const int* in_sizes, int n_in,
                              void* d_out, int out_size) {
    // Bind inputs by element count (robust to metadata ordering):
    //   meta_logits  128*65536   = 8388608   f32
    //   h_c          128*512     = 65536     f32
    //   embed_table  670001*512  = 343040512 f32
    //   label_clusters 65536*16  = 1048576   i32 (jax x64 disabled -> int32)
    const float* meta = nullptr;
    const float* hc = nullptr;
    const float* table = nullptr;
    const int* clusters = nullptr;
    for (int i = 0; i < n_in; i++) {
        switch (in_sizes[i]) {
            case 8388608:   meta     = (const float*)d_in[i]; break;
            case 65536:     hc       = (const float*)d_in[i]; break;
            case 343040512: table    = (const float*)d_in[i]; break;
            case 1048576:   clusters = (const int*)d_in[i];   break;
            default: break; // topk scalar etc.
        }
    }
    float* out = (float*)d_out; // 3 * 128 * 3200 f32: [cands | cand_scores | product]

    dim3 g1(SBn, Bn);
    collect_kernel<<<g1, 256>>>(meta);
    select_expand_kernel<<<Bn, 1024>>>(meta, clusters, out);
    dim3 g3(KMn / 32, Bn);
    score_kernel<<<g3, 256>>>(hc, table, out);
}

// round 7
// speedup vs baseline: 1.1726x; 1.0197x over previous
#include <cuda_runtime.h>

#define NUMLAB 670000
#define Bn 128
#define Cn 65536
#define Mn 16
#define Hn 512
#define Kn 200
#define KMn 3200        // Kn*Mn
#define SBn 8           // scan segments per row
#define SEGCAP 256      // survivor capacity per segment (expected ~50)
#define ROWCAP (SBn * SEGCAP)  // 2048

// ---- scratch (no allocations allowed) ----
__device__ int      g_scnt[Bn * SBn];
__device__ unsigned g_su[Bn * SBn * SEGCAP];
__device__ int      g_si[Bn * SBn * SEGCAP];
__device__ int      g_cands[Bn * KMn];
__device__ float    g_cscores[Bn * KMn];

// monotone float->uint key: descending float == descending key
__device__ __forceinline__ unsigned fkey(float x) {
    unsigned u = __float_as_uint(x);
    return (u & 0x80000000u) ? ~u : (u | 0x80000000u);
}

// ============================================================
// Kernel 1: full-chip streaming collect. grid (SBn, Bn), 256 thr.
// Each thread front-loads 8 independent float4 (max bytes in
// flight), filters 32 values against the raw-logit threshold
// (2.5), stages survivors in smem, dumps coalesced to a private
// per-segment global slot. No global atomics.
// ============================================================
__global__ void __launch_bounds__(256) collect_kernel(const float* __restrict__ logits) {
    const int row = blockIdx.y;
    const int seg = blockIdx.x;
    const int n4  = Cn / 4 / SBn;                 // 2048 float4 per block
    const float4* rp4 = (const float4*)(logits + (size_t)row * Cn) + seg * n4;
    const int base = seg * n4 * 4;
    const int tid = threadIdx.x;

    __shared__ unsigned s_u[SEGCAP];
    __shared__ int      s_i[SEGCAP];
    __shared__ int      s_cnt;
    if (tid == 0) s_cnt = 0;
    __syncthreads();

    // 8 independent loads in flight
    float4 a[8];
    #pragma unroll
    for (int k = 0; k < 8; k++) a[k] = rp4[tid + 256 * k];

    #pragma unroll
    for (int k = 0; k < 8; k++) {
        float vals[4] = {a[k].x, a[k].y, a[k].z, a[k].w};
        #pragma unroll
        for (int t = 0; t < 4; t++) {
            if (vals[t] > 2.5f) {
                int p = atomicAdd(&s_cnt, 1);
                if (p < SEGCAP) {
                    s_u[p] = fkey(vals[t]);
                    s_i[p] = base + (k * 256 + tid) * 4 + t;
                }
            }
        }
    }
    __syncthreads();
    const int c  = s_cnt;
    const int cc = min(c, SEGCAP);
    const size_t off = (size_t)(row * SBn + seg) * SEGCAP;
    if (tid < cc) {
        g_su[off + tid] = s_u[tid];
        g_si[off + tid] = s_i[tid];
    }
    if (tid == 0) g_scnt[row * SBn + seg] = c;
}

// ============================================================
// Kernel 2: per-row exact top-200 rank-select over survivors
// (value desc, index-asc ties) FUSED with cluster expansion +
// stable pad-compaction. One block (1024 thr) per row.
// Rank-select is warp-cooperative: warp per survivor, lanes
// split the comparison scan, shfl-reduce the rank.
// Fallback (block-uniform trigger: any segment overflow, or
// total < Kn): exact 4x8-bit radix select re-scanning the row.
// ============================================================
__global__ void __launch_bounds__(1024) select_expand_kernel(const float* __restrict__ logits,
                                                             const int* __restrict__ clusters,
                                                             float* __restrict__ out) {
    const int row = blockIdx.x;
    const int tid = threadIdx.x;
    const int lane = tid & 31;
    const int wid  = tid >> 5;
    const float*  rp  = logits + (size_t)row * Cn;
    const float4* rp4 = (const float4*)rp;

    __shared__ unsigned s_bu[ROWCAP];      // 8 KB
    __shared__ int      s_bi[ROWCAP];      // 8 KB
    __shared__ int      s_segcnt[SBn];
    __shared__ int      s_segoff[SBn + 1];
    __shared__ int      s_tidx[Kn];
    __shared__ float    s_tsc[Kn];
    __shared__ int      s_wsum[32];
    __shared__ int      s_total;
    __shared__ unsigned s_red[256];
    __shared__ unsigned s_prefix;
    __shared__ int      s_kneed;
    __shared__ int      s_cnt;
    __shared__ int      s_bad;

    // parallel load of per-segment counts
    if (tid < SBn) s_segcnt[tid] = g_scnt[row * SBn + tid];
    __syncthreads();
    if (tid == 0) {
        int acc = 0, bad = 0;
        #pragma unroll
        for (int s = 0; s < SBn; s++) {
            s_segoff[s] = acc;
            int c = s_segcnt[s];
            if (c > SEGCAP) bad = 1;
            acc += min(c, SEGCAP);
        }
        s_segoff[SBn] = acc;
        if (acc < Kn) bad = 1;
        s_bad = bad;
    }
    __syncthreads();

    int m;
    if (!s_bad) {
        m = s_segoff[SBn];
        // coalesced gather: 128 threads per segment
        {
            const int s  = tid >> 7;            // 0..7
            const int lt = tid & 127;
            const int cnt = s_segoff[s + 1] - s_segoff[s];
            const size_t off = (size_t)(row * SBn + s) * SEGCAP;
            for (int i = lt; i < cnt; i += 128) {
                s_bu[s_segoff[s] + i] = g_su[off + i];
                s_bi[s_segoff[s] + i] = g_si[off + i];
            }
        }
        __syncthreads();
    } else {
        // ---- fallback: exact radix select of the Kn-th largest key ----
        if (tid == 0) { s_prefix = 0u; s_kneed = Kn; s_cnt = 0; }
        __syncthreads();
        for (int shift = 24; shift >= 0; shift -= 8) {
            for (int b = tid; b < 256; b += 1024) s_red[b] = 0u;
            __syncthreads();
            const unsigned pref = s_prefix;
            const unsigned mhi  = (shift == 24) ? 0u : (0xFFFFFFFFu << (shift + 8));
            for (int i = tid; i < Cn / 4; i += 1024) {
                float4 v = rp4[i];
                float vals[4] = {v.x, v.y, v.z, v.w};
                #pragma unroll
                for (int t = 0; t < 4; t++) {
                    unsigned u = fkey(vals[t]);
                    if ((u & mhi) == pref) atomicAdd(&s_red[(u >> shift) & 255], 1u);
                }
            }
            __syncthreads();
            if (tid == 0) {
                int kneed = s_kneed;
                int cum = 0;
                int b = 255;
                for (; b > 0; b--) {
                    int c = (int)s_red[b];
                    if (cum + c >= kneed) break;
                    cum += c;
                }
                s_kneed  = kneed - cum;
                s_prefix = pref | ((unsigned)b << shift);
            }
            __syncthreads();
        }
        const unsigned T = s_prefix;
        for (int i = tid; i < Cn / 4; i += 1024) {
            float4 v = rp4[i];
            float vals[4] = {v.x, v.y, v.z, v.w};
            #pragma unroll
            for (int t = 0; t < 4; t++) {
                unsigned u = fkey(vals[t]);
                if (u >= T) {
                    int p = atomicAdd(&s_cnt, 1);
                    if (p < ROWCAP) { s_bu[p] = u; s_bi[p] = i * 4 + t; }
                }
            }
        }
        __syncthreads();
        m = min(s_cnt, ROWCAP);
    }

    // ---- warp-cooperative exact rank-select ----
    // rank(i) = #{j : u_j > u_i or (u_j == u_i and idx_j < idx_i)}
    for (int i = wid; i < m; i += 32) {
        const unsigned ui = s_bu[i];
        const int xi = s_bi[i];
        int r = 0;
        for (int j = lane; j < m; j += 32) {
            const unsigned uj = s_bu[j];
            r += (uj > ui || (uj == ui && s_bi[j] < xi)) ? 1 : 0;
        }
        #pragma unroll
        for (int off = 16; off; off >>= 1)
            r += __shfl_xor_sync(0xffffffffu, r, off);
        if (lane == 0 && r < Kn) {
            float v = rp[xi];
            s_tidx[r] = xi;
            s_tsc[r]  = 1.f / (1.f + __expf(-v));
        }
    }
    __syncthreads();

    // ---- expand clusters + stable pad-compaction ----
    int cand[4];
    int valid[4];
    float sc = 0.f;
    const int base = tid * 4;
    int nv = 0;
    if (base < KMn) {
        const int j = base >> 4;                 // 4 | 16 => same topk slot for all 4
        const int idx = min(max(s_tidx[j], 0), Cn - 1);
        sc = s_tsc[j];
        const int mb = base & 15;
        #pragma unroll
        for (int t = 0; t < 4; t++) {
            int c = clusters[(size_t)idx * Mn + mb + t];
            cand[t]  = c;
            valid[t] = (c != NUMLAB);
            nv += valid[t];
        }
    }
    // warp-shuffle inclusive scan of nv, then 32-warp scan in warp 0
    int x = nv;
    #pragma unroll
    for (int off = 1; off < 32; off <<= 1) {
        int y = __shfl_up_sync(0xffffffffu, x, off);
        if (lane >= off) x += y;
    }
    if (lane == 31) s_wsum[wid] = x;
    __syncthreads();
    if (tid < 32) {
        int v = s_wsum[tid];
        int inc = v;
        #pragma unroll
        for (int off = 1; off < 32; off <<= 1) {
            int y = __shfl_up_sync(0xffffffffu, inc, off);
            if (tid >= off) inc += y;
        }
        s_wsum[tid] = inc - v;   // exclusive warp offset
        if (tid == 31) s_total = inc;
    }
    __syncthreads();
    const int total = s_total;
    const int excl  = s_wsum[wid] + x - nv;

    if (base < KMn) {
        int vb = excl;  // valids strictly before current element
        #pragma unroll
        for (int t = 0; t < 4; t++) {
            int pos;
            if (valid[t]) { pos = vb; vb++; }
            else          { pos = total + (base + t) - vb; }
            g_cands[row * KMn + pos]   = cand[t];
            g_cscores[row * KMn + pos] = valid[t] ? sc : 0.f;
            out[(size_t)row * KMn + pos] = (float)cand[t];
        }
    }
}

// ============================================================
// Kernel 3: gather embeddings + dot with h_c, sigmoid, outputs.
// Warp per candidate (4 per warp), h_c row in smem.
// (Measured at the LTS/DRAM cap — do not touch.)
// ============================================================
__global__ void __launch_bounds__(256) score_kernel(const float* __restrict__ h_c,
                                                    const float* __restrict__ table,
                                                    float* __restrict__ out) {
    const int row = blockIdx.y;
    __shared__ float sh[Hn];
    for (int i = threadIdx.x; i < Hn; i += 256) sh[i] = h_c[(size_t)row * Hn + i];
    __syncthreads();

    const int warp = threadIdx.x >> 5;
    const int lane = threadIdx.x & 31;
    const int c0 = blockIdx.x * 32 + warp * 4;
    const float4* hv = (const float4*)sh;

    for (int t = 0; t < 4; t++) {
        const int c = c0 + t;
        int label = g_cands[row * KMn + c];
        label = min(max(label, 0), NUMLAB);
        const float4* er = (const float4*)(table + (size_t)label * Hn);
        float acc = 0.f;
        #pragma unroll
        for (int i = 0; i < 4; i++) {
            float4 e = er[lane + i * 32];
            float4 h = hv[lane + i * 32];
            acc += e.x * h.x;
            acc += e.y * h.y;
            acc += e.z * h.z;
            acc += e.w * h.w;
        }
        #pragma unroll
        for (int off = 16; off; off >>= 1)
            acc += __shfl_xor_sync(0xffffffffu, acc, off);
        if (lane == 0) {
            float s = (acc == 0.f) ? 0.f : (1.f / (1.f + __expf(-acc)));
            out[(size_t)Bn * KMn     + (size_t)row * KMn + c] = s;
            out[(size_t)Bn * KMn * 2 + (size_t)row * KMn + c] = s * g_cscores[row * KMn + c];
        }
    }
}

extern "C" void kernel_launch(void* const* d_in, const int* in_sizes, int n_in,
                              void* d_out, int out_size) {
    // Bind inputs by element count (robust to metadata ordering):
    //   meta_logits  128*65536   = 8388608   f32
    //   h_c          128*512     = 65536     f32
    //   embed_table  670001*512  = 343040512 f32
    //   label_clusters 65536*16  = 1048576   i32 (jax x64 disabled -> int32)
    const float* meta = nullptr;
    const float* hc = nullptr;
    const float* table = nullptr;
    const int* clusters = nullptr;
    for (int i = 0; i < n_in; i++) {
        switch (in_sizes[i]) {
            case 8388608:   meta     = (const float*)d_in[i]; break;
            case 65536:     hc       = (const float*)d_in[i]; break;
            case 343040512: table    = (const float*)d_in[i]; break;
            case 1048576:   clusters = (const int*)d_in[i];   break;
            default: break; // topk scalar etc.
        }
    }
    float* out = (float*)d_out; // 3 * 128 * 3200 f32: [cands | cand_scores | product]

    dim3 g1(SBn, Bn);
    collect_kernel<<<g1, 256>>>(meta);
    select_expand_kernel<<<Bn, 1024>>>(meta, clusters, out);
    dim3 g3(KMn / 32, Bn);
    score_kernel<<<g3, 256>>>(hc, table, out);
}